// round 2
// baseline (speedup 1.0000x reference)
#include <cuda_runtime.h>
#include <math.h>

#define P      512
#define K_MAX  16
#define NB     16
#define KC     32
#define M_CAP  65536

// ---------------- device scratch (static: no allocations allowed) ----------
__device__ int   d_cnt[K_MAX];
__device__ int   d_kval;
__device__ int   d_is64;
__device__ int   d_cls[M_CAP];
__device__ float d_Gk[K_MAX][P][P];
__device__ float d_A[K_MAX + 1][P * P];
__device__ float d_hld[K_MAX + 1];

// ------- init: zero counts, read num_classes, detect Y dtype (i32 vs i64) --
// int64 labels in [0,10) have all high (odd 32-bit) words == 0; int32 labels
// put real labels (~90% nonzero) at odd words. Scan first 1024 words (safe
// for both layouts: >= 4KB in either case).
__global__ void k_init(const int* ncls, const int* yw) {
    __shared__ int nz;
    int t = threadIdx.x;
    if (t == 0) nz = 0;
    __syncthreads();
    int found = 0;
    for (int i = t; i < 512; i += blockDim.x)
        if (yw[2 * i + 1] != 0) found = 1;
    if (__any_sync(0xffffffffu, found)) {
        if ((t & 31) == 0) atomicOr(&nz, 1);
    }
    __syncthreads();
    if (t < K_MAX) d_cnt[t] = 0;
    if (t == 0) {
        d_is64 = nz ? 0 : 1;
        int k = ncls ? *ncls : 10;
        if (k < 1) k = 1;
        if (k > K_MAX) k = K_MAX;
        d_kval = k;
    }
}

// ---------------- prep: labels -> int32 array, class histogram --------------
__global__ void k_prep(const void* __restrict__ Y, int m) {
    int i = blockIdx.x * blockDim.x + threadIdx.x;
    if (i >= m || i >= M_CAP) return;
    int cv = d_is64 ? (int)((const long long*)Y)[i] : ((const int*)Y)[i];
    d_cls[i] = cv;
    if (cv >= 0 && cv < K_MAX) atomicAdd(&d_cnt[cv], 1);
}

// ---------------- per-class Gram: Gk[c] = sum_{i: y_i=c} x_i x_i^T ---------
// grid: (10 lower 128x128 tiles, K_MAX classes), 256 threads, 8x8 micro-tile.
__global__ __launch_bounds__(256) void k_gram(const float* __restrict__ X,
                                              int m, int p) {
    int c = blockIdx.y;
    if (c >= d_kval) return;
    int tile = blockIdx.x;                  // lower-triangular 128-tile index
    int ti = 0;
    while ((ti + 1) * (ti + 2) / 2 <= tile) ti++;
    int tj = tile - ti * (ti + 1) / 2;
    int a0 = ti * 128, b0 = tj * 128;

    __shared__ __align__(16) float sA[KC][132];
    __shared__ __align__(16) float sB[KC][132];
    __shared__ int scls[KC];

    int tid = threadIdx.x;
    int tx = tid & 15, ty = tid >> 4;       // 16x16 thread grid
    int lt = tid >> 3, lc = tid & 7;        // load mapping: row t, col group

    float acc[8][8];
#pragma unroll
    for (int i = 0; i < 8; i++)
#pragma unroll
        for (int j = 0; j < 8; j++) acc[i][j] = 0.f;

    for (int base = 0; base < m; base += KC) {
        if (tid < KC) {
            int s = base + tid;
            scls[tid] = (s < m) ? d_cls[s] : -1;
        }
        __syncthreads();

        // gathered loads: only rows whose class matches
        {
            int s = base + lt;
            if (scls[lt] == c) {
                const float* xr = X + (size_t)s * p;
#pragma unroll
                for (int q = 0; q < 4; q++) {
                    int col = lc * 16 + q * 4;
                    *(float4*)&sA[lt][col] = *(const float4*)&xr[a0 + col];
                    *(float4*)&sB[lt][col] = *(const float4*)&xr[b0 + col];
                }
            }
        }
        __syncthreads();

#pragma unroll 8
        for (int t = 0; t < KC; t++) {
            if (scls[t] != c) continue;     // warp-uniform skip
            float a[8], b[8];
            *(float4*)&a[0] = *(const float4*)&sA[t][ty * 8];
            *(float4*)&a[4] = *(const float4*)&sA[t][ty * 8 + 4];
            *(float4*)&b[0] = *(const float4*)&sB[t][tx * 8];
            *(float4*)&b[4] = *(const float4*)&sB[t][tx * 8 + 4];
#pragma unroll
            for (int ii = 0; ii < 8; ii++)
#pragma unroll
                for (int jj = 0; jj < 8; jj++)
                    acc[ii][jj] = fmaf(a[ii], b[jj], acc[ii][jj]);
        }
        __syncthreads();
    }

    float* G = &d_Gk[c][0][0];
    int gi = a0 + ty * 8, gj = b0 + tx * 8;
#pragma unroll
    for (int ii = 0; ii < 8; ii++) {
        *(float4*)&G[(size_t)(gi + ii) * P + gj]     = *(float4*)&acc[ii][0];
        *(float4*)&G[(size_t)(gi + ii) * P + gj + 4] = *(float4*)&acc[ii][4];
    }
    if (ti != tj) {                          // mirror to upper triangle
#pragma unroll
        for (int ii = 0; ii < 8; ii++)
#pragma unroll
            for (int jj = 0; jj < 8; jj++)
                G[(size_t)(gj + jj) * P + gi + ii] = acc[ii][jj];
    }
}

// ---------------- assemble A_j = I + scal_j*Gk_j, A_k = I + scalar*G -------
__global__ void k_assemble(int m, float pf) {
    int idx = blockIdx.x * blockDim.x + threadIdx.x;
    if (idx >= P * P) return;
    int r = idx >> 9, cc = idx & 511;
    int kv = d_kval;
    float diag = (r == cc) ? 1.f : 0.f;
    float sum = 0.f;
    for (int j = 0; j < kv; j++) {
        float g = d_Gk[j][r][cc];
        sum += g;
        float trPi = (float)d_cnt[j] + 1e-8f;
        float scal = pf / (trPi * 0.01f);
        d_A[j][idx] = diag + scal * g;
    }
    float scalar = pf / ((float)m * 0.01f);
    d_A[kv][idx] = diag + scalar * sum;
}

// ---------------- blocked Cholesky logdet, one CTA per matrix --------------
__global__ __launch_bounds__(256) void k_chol() {
    int mb = blockIdx.x;
    if (mb > d_kval) return;
    float* A = d_A[mb];

    __shared__ float sD[NB][NB + 1];
    __shared__ __align__(16) float sP[NB][500];   // panel, rows of 500 floats
    __shared__ double sLog;

    int tid = threadIdx.x;
    if (tid == 0) sLog = 0.0;

    for (int s = 0; s < P / NB; s++) {
        int sc = s * NB;

        // load diagonal block
        for (int l = tid; l < NB * NB; l += blockDim.x) {
            int r = l / NB, c = l % NB;
            sD[r][c] = A[(size_t)(sc + r) * P + sc + c];
        }
        __syncthreads();

        // warp-0 factors the 16x16 diagonal block (reads lower only)
        if (tid < 32) {
#pragma unroll
            for (int t = 0; t < NB; t++) {
                if (tid == 0) sD[t][t] = sqrtf(sD[t][t]);
                __syncwarp();
                float dinv = 1.f / sD[t][t];
                if (tid > t && tid < NB) sD[tid][t] *= dinv;
                __syncwarp();
                for (int l = tid; l < NB * NB; l += 32) {
                    int i = l / NB, u = l % NB;
                    if (u > t && i >= u) sD[i][u] -= sD[i][t] * sD[u][t];
                }
                __syncwarp();
            }
            double lsum = (tid < NB) ? (double)logf(sD[tid][tid]) : 0.0;
#pragma unroll
            for (int o = 16; o > 0; o >>= 1)
                lsum += __shfl_down_sync(0xffffffffu, lsum, o);
            if (tid == 0) sLog += lsum;
        }
        __syncthreads();

        int rem = P - sc - NB;
        if (rem > 0) {
            // panel solve: rows below diag block; deposit into shared sP[t][row]
            for (int rr = tid; rr < rem; rr += blockDim.x) {
                int row = sc + NB + rr;
                const float* Ar = &A[(size_t)row * P + sc];
                float x[NB];
#pragma unroll
                for (int t = 0; t < NB; t++) x[t] = Ar[t];
#pragma unroll
                for (int t = 0; t < NB; t++) {
                    float v = x[t];
#pragma unroll
                    for (int u = 0; u < t; u++) v -= x[u] * sD[t][u];
                    v /= sD[t][t];
                    x[t] = v;
                    sP[t][rr] = v;
                }
            }
            __syncthreads();

            // trailing update: A[i][j] -= sum_t P[t][i]*P[t][j], lower 8x8 tiles
            int rem8 = rem >> 3;
            int ntile = rem8 * (rem8 + 1) / 2;
            for (int l = tid; l < ntile; l += blockDim.x) {
                int ti = (int)((sqrtf(8.f * (float)l + 1.f) - 1.f) * 0.5f);
                while ((ti + 1) * (ti + 2) / 2 <= l) ti++;
                while (ti * (ti + 1) / 2 > l) ti--;
                int tj = l - ti * (ti + 1) / 2;
                int i0 = ti * 8, j0 = tj * 8;

                float acc[8][8];
#pragma unroll
                for (int ii = 0; ii < 8; ii++)
#pragma unroll
                    for (int jj = 0; jj < 8; jj++) acc[ii][jj] = 0.f;

#pragma unroll
                for (int t = 0; t < NB; t++) {
                    float a[8], b[8];
                    *(float4*)&a[0] = *(const float4*)&sP[t][i0];
                    *(float4*)&a[4] = *(const float4*)&sP[t][i0 + 4];
                    *(float4*)&b[0] = *(const float4*)&sP[t][j0];
                    *(float4*)&b[4] = *(const float4*)&sP[t][j0 + 4];
#pragma unroll
                    for (int ii = 0; ii < 8; ii++)
#pragma unroll
                        for (int jj = 0; jj < 8; jj++)
                            acc[ii][jj] = fmaf(a[ii], b[jj], acc[ii][jj]);
                }

                int gr = sc + NB + i0, gc = sc + NB + j0;
#pragma unroll
                for (int ii = 0; ii < 8; ii++) {
                    float* row = &A[(size_t)(gr + ii) * P + gc];
                    float4 v0 = *(float4*)&row[0];
                    float4 v1 = *(float4*)&row[4];
                    v0.x -= acc[ii][0]; v0.y -= acc[ii][1];
                    v0.z -= acc[ii][2]; v0.w -= acc[ii][3];
                    v1.x -= acc[ii][4]; v1.y -= acc[ii][5];
                    v1.z -= acc[ii][6]; v1.w -= acc[ii][7];
                    *(float4*)&row[0] = v0;
                    *(float4*)&row[4] = v1;
                }
            }
        }
        __syncthreads();
    }

    if (tid == 0) d_hld[mb] = (float)sLog;   // half-logdet = sum log(L_ii)
}

// ---------------- finalize: two scalars ------------------------------------
__global__ void k_final(float* out, int m) {
    if (threadIdx.x != 0) return;
    int kv = d_kval;
    float comp = 0.f;
    for (int j = 0; j < kv; j++) {
        float trPi = (float)d_cnt[j] + 1e-8f;
        comp += d_hld[j] * trPi / (float)m;   // (2*hld)*trPi/m / 2
    }
    out[0] = d_hld[kv];                       // slogdet/2 of global term
    out[1] = comp;
}

// ---------------- launch ----------------------------------------------------
extern "C" void kernel_launch(void* const* d_in, const int* in_sizes, int n_in,
                              void* d_out, int out_size) {
    const float* X    = (const float*)d_in[0];
    const void*  Y    = d_in[1];
    const int*   ncls = (n_in >= 3) ? (const int*)d_in[2] : nullptr;
    int m = in_sizes[1];
    int p = in_sizes[0] / m;          // 512
    float* out = (float*)d_out;
    (void)out_size;

    k_init<<<1, 256>>>(ncls, (const int*)Y);
    k_prep<<<(m + 255) / 256, 256>>>(Y, m);
    k_gram<<<dim3(10, K_MAX), 256>>>(X, m, p);
    k_assemble<<<(P * P + 255) / 256, 256>>>(m, (float)p);
    k_chol<<<K_MAX + 1, 256>>>();
    k_final<<<1, 32>>>(out, m);
}